// round 8
// baseline (speedup 1.0000x reference)
#include <cuda_runtime.h>
#include <cstdint>
#include <math.h>

#define NN 16
#define TT 800
#define FF 90
#define SS 128
#define LL 200
#define NEGF (-1e30f)

// per-utterance scores scratch (device globals: no allocation allowed)
__device__ float g_den[NN];
__device__ float g_num[NN];

// ---- packed fp32x2 helpers (sm_103a) ----
__device__ __forceinline__ unsigned long long fma_f32x2(unsigned long long a,
                                                        unsigned long long b,
                                                        unsigned long long c) {
    unsigned long long d;
    asm("fma.rn.f32x2 %0, %1, %2, %3;" : "=l"(d) : "l"(a), "l"(b), "l"(c));
    return d;
}
__device__ __forceinline__ unsigned long long add_f32x2(unsigned long long a,
                                                        unsigned long long b) {
    unsigned long long d;
    asm("add.rn.f32x2 %0, %1, %2;" : "=l"(d) : "l"(a), "l"(b));
    return d;
}
__device__ __forceinline__ unsigned long long pack2(float lo, float hi) {
    unsigned long long d;
    asm("mov.b64 %0, {%1, %2};" : "=l"(d) : "f"(lo), "f"(hi));
    return d;
}
__device__ __forceinline__ float2 unpack2(unsigned long long v) {
    float lo, hi;
    asm("mov.b64 {%0, %1}, %2;" : "=f"(lo), "=f"(hi) : "l"(v));
    return make_float2(lo, hi);
}

// blocks 0..7:  den for utterance pair (b, b+8). 128 threads, 1 state/thread,
//               full K column in registers (shared by both utterances).
// blocks 8..23: num for utterance b-8. 128 threads, 2 chain states/thread.
__global__ __launch_bounds__(128, 1)
void mmi_forward(const float* __restrict__ nnet,   // [N, T, F] log-softmax
                 const int*   __restrict__ sup,    // [N, 3]
                 const float* __restrict__ trans,  // [S, S]
                 const int*   __restrict__ dlab,   // [S]
                 const int*   __restrict__ nlab,   // [N, L]
                 const int*   __restrict__ nlens)  // [N]
{
    __shared__ __align__(16) float sh_vA[2][SS];
    __shared__ __align__(16) float sh_vB[2][SS];
    __shared__ float sh_wsum[2][4];
    __shared__ float sh_a[2][LL + 8];

    const int tid = threadIdx.x;
    const int b   = blockIdx.x;

    if (b < 8) {
        // ======= denominator forward: two utterances per CTA, linear space ====
        const int nA = b;
        const int nB = b + 8;
        const int nfA = sup[nA * 3 + 2];
        const int nfB = sup[nB * 3 + 2];
        const int nfMax = (nfA > nfB) ? nfA : nfB;
        const int s = tid;                  // one output state per thread

        // Full E column (128 k-values) in registers, packed f32x2 (128 regs).
        unsigned long long E2[64];
        #pragma unroll 8
        for (int j = 0; j < 64; ++j) {
            E2[j] = pack2(expf(trans[(2 * j) * SS + s]),
                          expf(trans[(2 * j + 1) * SS + s]));
        }
        const int lab = dlab[s];
        const float* bA = nnet + (long long)nA * TT * FF + lab;
        const float* bB = nnet + (long long)nB * TT * FF + lab;
        float lpA  = __ldg(bA);       float lpB  = __ldg(bB);
        float lpA1 = __ldg(bA + FF);  float lpB1 = __ldg(bB + FF);

        sh_vA[0][s] = (s == 0) ? 1.0f : 0.0f;
        sh_vB[0][s] = (s == 0) ? 1.0f : 0.0f;
        __syncthreads();

        int cur = 0;
        int MexpA = 0, MexpB = 0;

        for (int t = 0; t < nfMax; ++t) {
            // v[0] exponent -> exact 2^-e rescale (uniform: broadcast reads)
            const float v0A = sh_vA[cur][0];
            const float v0B = sh_vB[cur][0];
            const float oldA = sh_vA[cur][s];      // for frozen frames
            const float oldB = sh_vB[cur][s];
            const int ebA = (int)(__float_as_uint(v0A) >> 23);
            const int ebB = (int)(__float_as_uint(v0B) >> 23);
            const float psA = __expf(lpA) *
                              __uint_as_float((unsigned)(254 - ebA) << 23);
            const float psB = __expf(lpB) *
                              __uint_as_float((unsigned)(254 - ebB) << 23);

            const int tn = (t + 2 < TT) ? (t + 2) : (TT - 1);
            const float lpA2 = __ldg(bA + (long long)tn * FF);  // prefetch d=2
            const float lpB2 = __ldg(bB + (long long)tn * FF);

            // interleaved dual matvec: E2[j] reused by both utterances
            const ulonglong2* vpA =
                reinterpret_cast<const ulonglong2*>(&sh_vA[cur][0]);
            const ulonglong2* vpB =
                reinterpret_cast<const ulonglong2*>(&sh_vB[cur][0]);

            unsigned long long aA0 = 0ull, aA1 = 0ull, aA2 = 0ull, aA3 = 0ull;
            unsigned long long aB0 = 0ull, aB1 = 0ull, aB2 = 0ull, aB3 = 0ull;
            #pragma unroll
            for (int i = 0; i < 32; ++i) {
                const ulonglong2 qa = vpA[i];
                const ulonglong2 qb = vpB[i];
                if (i & 1) {
                    aA2 = fma_f32x2(qa.x, E2[2 * i],     aA2);
                    aA3 = fma_f32x2(qa.y, E2[2 * i + 1], aA3);
                    aB2 = fma_f32x2(qb.x, E2[2 * i],     aB2);
                    aB3 = fma_f32x2(qb.y, E2[2 * i + 1], aB3);
                } else {
                    aA0 = fma_f32x2(qa.x, E2[2 * i],     aA0);
                    aA1 = fma_f32x2(qa.y, E2[2 * i + 1], aA1);
                    aB0 = fma_f32x2(qb.x, E2[2 * i],     aB0);
                    aB1 = fma_f32x2(qb.y, E2[2 * i + 1], aB1);
                }
            }
            aA0 = add_f32x2(aA0, aA2);  aA1 = add_f32x2(aA1, aA3);
            aB0 = add_f32x2(aB0, aB2);  aB1 = add_f32x2(aB1, aB3);
            aA0 = add_f32x2(aA0, aA1);  aB0 = add_f32x2(aB0, aB1);
            const float2 uA = unpack2(aA0);
            const float2 uB = unpack2(aB0);
            const float dotA = uA.x + uA.y;
            const float dotB = uB.x + uB.y;

            const bool actA = (t < nfA);
            const bool actB = (t < nfB);
            sh_vA[cur ^ 1][s] = actA ? dotA * psA : oldA;
            sh_vB[cur ^ 1][s] = actB ? dotB * psB : oldB;
            MexpA += actA ? (ebA - 127) : 0;
            MexpB += actB ? (ebB - 127) : 0;

            lpA = lpA1;  lpA1 = lpA2;
            lpB = lpB1;  lpB1 = lpB2;
            __syncthreads();
            cur ^= 1;
        }

        // den = Mexp*ln2 + log(sum v), both utterances
        {
            float vA = sh_vA[cur][s];
            float vB = sh_vB[cur][s];
            #pragma unroll
            for (int o = 16; o; o >>= 1) {
                vA += __shfl_xor_sync(0xffffffffu, vA, o);
                vB += __shfl_xor_sync(0xffffffffu, vB, o);
            }
            if ((tid & 31) == 0) {
                sh_wsum[0][tid >> 5] = vA;
                sh_wsum[1][tid >> 5] = vB;
            }
        }
        __syncthreads();
        if (tid == 0) {
            const float sA = sh_wsum[0][0] + sh_wsum[0][1] +
                             sh_wsum[0][2] + sh_wsum[0][3];
            const float sB = sh_wsum[1][0] + sh_wsum[1][1] +
                             sh_wsum[1][2] + sh_wsum[1][3];
            g_den[nA] = (float)((double)MexpA * 0.6931471805599453 +
                                (double)logf(sA));
            g_den[nB] = (float)((double)MexpB * 0.6931471805599453 +
                                (double)logf(sB));
        }
    } else {
        // ============ numerator forward (log space), 2 states/thread ==========
        const int n  = b - 8;
        const int nf = sup[n * 3 + 2];
        const int qi = nlens[n];
        const int i  = tid;                 // 0..127; active i < 100

        // thread i owns states l0 = 2i+1 and l1 = 2i+2
        const float* lpb0 = nnet;  // dummy init
        const float* lpb1 = nnet;
        float lpA = 0.f, lpA1 = 0.f, lpB = 0.f, lpB1 = 0.f;

        if (i < 100) {
            const long long base = (long long)n * TT * FF;
            lpb0 = nnet + base + nlab[n * LL + 2 * i];       // emit for l0
            lpb1 = nnet + base + nlab[n * LL + 2 * i + 1];   // emit for l1
            lpA  = __ldg(lpb0);       lpB  = __ldg(lpb1);
            lpA1 = __ldg(lpb0 + FF);  lpB1 = __ldg(lpb1 + FF);
        }
        for (int j = i; j <= LL; j += 128) {
            sh_a[0][j] = (j == 0) ? 0.0f : NEGF;
            sh_a[1][j] = NEGF;
        }
        int cur = 0;
        __syncthreads();

        for (int t = 0; t < nf; ++t) {
            if (i < 100) {
                const float am = sh_a[cur][2 * i];       // old alpha[l0-1]
                const float a0 = sh_a[cur][2 * i + 1];   // old alpha[l0]
                const float a1 = sh_a[cur][2 * i + 2];   // old alpha[l1]

                const float h0 = fmaxf(a0, am), l0v = fminf(a0, am);
                const float nv0 = h0 + __logf(1.0f + __expf(l0v - h0)) + lpA;
                const float h1 = fmaxf(a1, a0), l1v = fminf(a1, a0);
                const float nv1 = h1 + __logf(1.0f + __expf(l1v - h1)) + lpB;

                const int   tn = (t + 2 < TT) ? (t + 2) : (TT - 1);
                const float pA = __ldg(lpb0 + (long long)tn * FF);
                const float pB = __ldg(lpb1 + (long long)tn * FF);

                sh_a[cur ^ 1][2 * i + 1] = nv0;
                sh_a[cur ^ 1][2 * i + 2] = nv1;
                if (i == 0) sh_a[cur ^ 1][0] = NEGF;     // alpha[0] = NEG each step
                lpA = lpA1; lpA1 = pA;
                lpB = lpB1; lpB1 = pB;
            }
            __syncthreads();
            cur ^= 1;
        }
        if (i == 0) g_num[n] = sh_a[cur][qi];
    }
}

__global__ void mmi_finalize(const int* __restrict__ sup, float* __restrict__ out)
{
    const int tid = threadIdx.x;  // 32 threads
    float tot = 0.f, fr = 0.f, af = 0.f;
    if (tid < NN) {
        const int nf = sup[tid * 3 + 2];
        const float t = g_num[tid] - g_den[tid];
        const bool fin = isfinite(t) && (t > 0.5f * NEGF);
        tot = fin ? t : 0.f;
        fr  = fin ? (float)nf : 0.f;
        af  = (float)nf;
    }
    #pragma unroll
    for (int o = 16; o; o >>= 1) {
        tot += __shfl_xor_sync(0xffffffffu, tot, o);
        fr  += __shfl_xor_sync(0xffffffffu, fr, o);
        af  += __shfl_xor_sync(0xffffffffu, af, o);
    }
    if (tid == 0) {
        out[0] = tot;
        out[1] = fr;
        out[2] = af;
    }
}

extern "C" void kernel_launch(void* const* d_in, const int* in_sizes, int n_in,
                              void* d_out, int out_size)
{
    const float* nnet  = (const float*)d_in[0];
    const int*   sup   = (const int*)  d_in[1];
    const float* trans = (const float*)d_in[2];
    const int*   dlab  = (const int*)  d_in[3];
    const int*   nlab  = (const int*)  d_in[4];
    const int*   nlens = (const int*)  d_in[5];

    mmi_forward<<<24, 128>>>(nnet, sup, trans, dlab, nlab, nlens);
    mmi_finalize<<<1, 32>>>(sup, (float*)d_out);
}

// round 9
// speedup vs baseline: 1.6478x; 1.6478x over previous
#include <cuda_runtime.h>
#include <cstdint>
#include <math.h>

#define NN 16
#define TT 800
#define FF 90
#define SS 128
#define LL 200
#define NEGF (-1e30f)

// per-utterance scores scratch (device globals: no allocation allowed)
__device__ float g_den[NN];
__device__ float g_num[NN];

// ---- packed fp32x2 helpers (sm_103a) ----
__device__ __forceinline__ unsigned long long fma_f32x2(unsigned long long a,
                                                        unsigned long long b,
                                                        unsigned long long c) {
    unsigned long long d;
    asm("fma.rn.f32x2 %0, %1, %2, %3;" : "=l"(d) : "l"(a), "l"(b), "l"(c));
    return d;
}
__device__ __forceinline__ unsigned long long add_f32x2(unsigned long long a,
                                                        unsigned long long b) {
    unsigned long long d;
    asm("add.rn.f32x2 %0, %1, %2;" : "=l"(d) : "l"(a), "l"(b));
    return d;
}
__device__ __forceinline__ unsigned long long pack2(float lo, float hi) {
    unsigned long long d;
    asm("mov.b64 %0, {%1, %2};" : "=l"(d) : "f"(lo), "f"(hi));
    return d;
}
__device__ __forceinline__ float2 unpack2(unsigned long long v) {
    float lo, hi;
    asm("mov.b64 {%0, %1}, %2;" : "=f"(lo), "=f"(hi) : "l"(v));
    return make_float2(lo, hi);
}

// blocks 0..15:  den for utterance b. 128 threads, one full state column per
//                thread (no SHFL, no half-combine; 4-warp barrier).
// blocks 16..31: num for utterance b-16. 128 threads, 2 chain states/thread.
__global__ __launch_bounds__(128, 1)
void mmi_forward(const float* __restrict__ nnet,   // [N, T, F] log-softmax
                 const int*   __restrict__ sup,    // [N, 3]
                 const float* __restrict__ trans,  // [S, S]
                 const int*   __restrict__ dlab,   // [S]
                 const int*   __restrict__ nlab,   // [N, L]
                 const int*   __restrict__ nlens)  // [N]
{
    __shared__ __align__(16) float sh_v[2][SS];
    __shared__ float sh_wsum[4];
    __shared__ float sh_a[2][LL + 8];

    const int tid = threadIdx.x;
    const int b   = blockIdx.x;

    if (b < NN) {
        // ======= denominator forward (scaled linear space), 1 state/thread ====
        const int n  = b;
        const int nf = sup[n * 3 + 2];
        const int s  = tid;                 // output state

        // Full E column (128 k-values) in registers, packed f32x2 (128 regs).
        unsigned long long E2[64];
        #pragma unroll 8
        for (int j = 0; j < 64; ++j) {
            E2[j] = pack2(expf(trans[(2 * j) * SS + s]),
                          expf(trans[(2 * j + 1) * SS + s]));
        }
        const int lab = dlab[s];
        const float* lp_base = nnet + (long long)n * TT * FF + lab;
        float lp  = __ldg(lp_base);                          // t = 0
        float lp1 = __ldg(lp_base + FF);                     // t = 1

        sh_v[0][s] = (s == 0) ? 1.0f : 0.0f;
        __syncthreads();

        int cur  = 0;
        int Mexp = 0;

        for (int t = 0; t < nf; ++t) {
            // exact 2^-e rescale keyed to v[0]'s exponent (uniform broadcast)
            const float v0 = sh_v[cur][0];
            const int   eb = (int)(__float_as_uint(v0) >> 23);     // biased exp
            const float ps = __expf(lp) *
                             __uint_as_float((unsigned)(254 - eb) << 23);
            Mexp += eb - 127;

            const int   tn   = (t + 2 < TT) ? (t + 2) : (TT - 1);
            const float lpn2 = __ldg(lp_base + (long long)tn * FF); // prefetch d=2

            const ulonglong2* vp =
                reinterpret_cast<const ulonglong2*>(&sh_v[cur][0]);

            // 64 FFMA2 across 8 accumulators, q loaded in 4 chunks of 8
            unsigned long long a0 = 0ull, a1 = 0ull, a2 = 0ull, a3 = 0ull;
            unsigned long long a4 = 0ull, a5 = 0ull, a6 = 0ull, a7 = 0ull;
            #pragma unroll
            for (int g = 0; g < 4; ++g) {
                ulonglong2 q[8];
                #pragma unroll
                for (int i = 0; i < 8; ++i) q[i] = vp[8 * g + i];
                #pragma unroll
                for (int i = 0; i < 4; ++i) {
                    a0 = fma_f32x2(q[2 * i].x,     E2[16 * g + 4 * i + 0], a0);
                    a1 = fma_f32x2(q[2 * i].y,     E2[16 * g + 4 * i + 1], a1);
                    a2 = fma_f32x2(q[2 * i + 1].x, E2[16 * g + 4 * i + 2], a2);
                    a3 = fma_f32x2(q[2 * i + 1].y, E2[16 * g + 4 * i + 3], a3);
                }
                // swap accumulator banks per chunk for dep distance
                unsigned long long tmp;
                tmp = a0; a0 = a4; a4 = tmp;
                tmp = a1; a1 = a5; a5 = tmp;
                tmp = a2; a2 = a6; a6 = tmp;
                tmp = a3; a3 = a7; a7 = tmp;
            }
            a0 = add_f32x2(a0, a4);
            a1 = add_f32x2(a1, a5);
            a2 = add_f32x2(a2, a6);
            a3 = add_f32x2(a3, a7);
            a0 = add_f32x2(a0, a2);
            a1 = add_f32x2(a1, a3);
            a0 = add_f32x2(a0, a1);
            const float2 u = unpack2(a0);
            const float dot = u.x + u.y;

            sh_v[cur ^ 1][s] = dot * ps;
            lp  = lp1;
            lp1 = lpn2;
            __syncthreads();
            cur ^= 1;
        }

        // den = Mexp*ln2 + log(sum v)
        {
            float v = sh_v[cur][s];
            #pragma unroll
            for (int o = 16; o; o >>= 1) v += __shfl_xor_sync(0xffffffffu, v, o);
            if ((tid & 31) == 0) sh_wsum[tid >> 5] = v;
        }
        __syncthreads();
        if (tid == 0) {
            const float sv = sh_wsum[0] + sh_wsum[1] + sh_wsum[2] + sh_wsum[3];
            g_den[n] = (float)((double)Mexp * 0.6931471805599453 +
                               (double)logf(sv));
        }
    } else {
        // ============ numerator forward (log space), 2 states/thread ==========
        const int n  = b - NN;
        const int nf = sup[n * 3 + 2];
        const int qi = nlens[n];
        const int i  = tid;                 // 0..127; active i < 100

        // thread i owns states l0 = 2i+1 and l1 = 2i+2
        const float* lpb0 = nnet;  // dummy init
        const float* lpb1 = nnet;
        float lpA = 0.f, lpA1 = 0.f, lpB = 0.f, lpB1 = 0.f;

        if (i < 100) {
            const long long base = (long long)n * TT * FF;
            lpb0 = nnet + base + nlab[n * LL + 2 * i];       // emit for l0
            lpb1 = nnet + base + nlab[n * LL + 2 * i + 1];   // emit for l1
            lpA  = __ldg(lpb0);       lpB  = __ldg(lpb1);
            lpA1 = __ldg(lpb0 + FF);  lpB1 = __ldg(lpb1 + FF);
        }
        for (int j = i; j <= LL; j += 128) {
            sh_a[0][j] = (j == 0) ? 0.0f : NEGF;
            sh_a[1][j] = NEGF;
        }
        int cur = 0;
        __syncthreads();

        for (int t = 0; t < nf; ++t) {
            if (i < 100) {
                const float am = sh_a[cur][2 * i];       // old alpha[l0-1]
                const float a0 = sh_a[cur][2 * i + 1];   // old alpha[l0]
                const float a1 = sh_a[cur][2 * i + 2];   // old alpha[l1]

                const float h0 = fmaxf(a0, am), l0v = fminf(a0, am);
                const float nv0 = h0 + __logf(1.0f + __expf(l0v - h0)) + lpA;
                const float h1 = fmaxf(a1, a0), l1v = fminf(a1, a0);
                const float nv1 = h1 + __logf(1.0f + __expf(l1v - h1)) + lpB;

                const int   tn = (t + 2 < TT) ? (t + 2) : (TT - 1);
                const float pA = __ldg(lpb0 + (long long)tn * FF);
                const float pB = __ldg(lpb1 + (long long)tn * FF);

                sh_a[cur ^ 1][2 * i + 1] = nv0;
                sh_a[cur ^ 1][2 * i + 2] = nv1;
                if (i == 0) sh_a[cur ^ 1][0] = NEGF;     // alpha[0] = NEG each step
                lpA = lpA1; lpA1 = pA;
                lpB = lpB1; lpB1 = pB;
            }
            __syncthreads();
            cur ^= 1;
        }
        if (i == 0) g_num[n] = sh_a[cur][qi];
    }
}

__global__ void mmi_finalize(const int* __restrict__ sup, float* __restrict__ out)
{
    const int tid = threadIdx.x;  // 32 threads
    float tot = 0.f, fr = 0.f, af = 0.f;
    if (tid < NN) {
        const int nf = sup[tid * 3 + 2];
        const float t = g_num[tid] - g_den[tid];
        const bool fin = isfinite(t) && (t > 0.5f * NEGF);
        tot = fin ? t : 0.f;
        fr  = fin ? (float)nf : 0.f;
        af  = (float)nf;
    }
    #pragma unroll
    for (int o = 16; o; o >>= 1) {
        tot += __shfl_xor_sync(0xffffffffu, tot, o);
        fr  += __shfl_xor_sync(0xffffffffu, fr, o);
        af  += __shfl_xor_sync(0xffffffffu, af, o);
    }
    if (tid == 0) {
        out[0] = tot;
        out[1] = fr;
        out[2] = af;
    }
}

extern "C" void kernel_launch(void* const* d_in, const int* in_sizes, int n_in,
                              void* d_out, int out_size)
{
    const float* nnet  = (const float*)d_in[0];
    const int*   sup   = (const int*)  d_in[1];
    const float* trans = (const float*)d_in[2];
    const int*   dlab  = (const int*)  d_in[3];
    const int*   nlab  = (const int*)  d_in[4];
    const int*   nlens = (const int*)  d_in[5];

    mmi_forward<<<2 * NN, 128>>>(nnet, sup, trans, dlab, nlab, nlens);
    mmi_finalize<<<1, 32>>>(sup, (float*)d_out);
}

// round 10
// speedup vs baseline: 1.6736x; 1.0156x over previous
#include <cuda_runtime.h>
#include <cstdint>
#include <math.h>

#define NN 16
#define TT 800
#define FF 90
#define SS 128
#define LL 200
#define NEGF (-1e30f)

// per-utterance scores scratch (device globals: no allocation allowed)
__device__ float g_den[NN];
__device__ float g_num[NN];

// ---- packed fp32x2 helpers (sm_103a) ----
__device__ __forceinline__ unsigned long long fma_f32x2(unsigned long long a,
                                                        unsigned long long b,
                                                        unsigned long long c) {
    unsigned long long d;
    asm("fma.rn.f32x2 %0, %1, %2, %3;" : "=l"(d) : "l"(a), "l"(b), "l"(c));
    return d;
}
__device__ __forceinline__ unsigned long long add_f32x2(unsigned long long a,
                                                        unsigned long long b) {
    unsigned long long d;
    asm("add.rn.f32x2 %0, %1, %2;" : "=l"(d) : "l"(a), "l"(b));
    return d;
}
__device__ __forceinline__ unsigned long long pack2(float lo, float hi) {
    unsigned long long d;
    asm("mov.b64 %0, {%1, %2};" : "=l"(d) : "f"(lo), "f"(hi));
    return d;
}
__device__ __forceinline__ float2 unpack2(unsigned long long v) {
    float lo, hi;
    asm("mov.b64 {%0, %1}, %2;" : "=f"(lo), "=f"(hi) : "l"(v));
    return make_float2(lo, hi);
}

// blocks 0..15:  den for utterance b. 128 threads, one full state column per
//                thread (no SHFL; 4-warp barrier).
// blocks 16..31: num for utterance b-16. 128 threads, 2 chain states/thread.
__global__ __launch_bounds__(128, 1)
void mmi_forward(const float* __restrict__ nnet,   // [N, T, F] log-softmax
                 const int*   __restrict__ sup,    // [N, 3]
                 const float* __restrict__ trans,  // [S, S]
                 const int*   __restrict__ dlab,   // [S]
                 const int*   __restrict__ nlab,   // [N, L]
                 const int*   __restrict__ nlens)  // [N]
{
    __shared__ __align__(16) float sh_v[2][SS];
    __shared__ float sh_wsum[4];
    __shared__ float sh_a[2][LL + 8];

    const int tid = threadIdx.x;
    const int b   = blockIdx.x;

    if (b < NN) {
        // ======= denominator forward (scaled linear space), 1 state/thread ====
        const int n  = b;
        const int nf = sup[n * 3 + 2];
        const int s  = tid;                 // output state

        // Full E column (128 k-values) in registers, packed f32x2 (128 regs).
        unsigned long long E2[64];
        #pragma unroll 8
        for (int j = 0; j < 64; ++j) {
            E2[j] = pack2(expf(trans[(2 * j) * SS + s]),
                          expf(trans[(2 * j + 1) * SS + s]));
        }
        const int lab = dlab[s];
        const float* lp_base = nnet + (long long)n * TT * FF + lab;
        float lp  = __ldg(lp_base);                          // t = 0
        float lp1 = __ldg(lp_base + FF);                     // t = 1

        sh_v[0][s] = (s == 0) ? 1.0f : 0.0f;
        __syncthreads();

        int cur  = 0;
        int Mexp = 0;

        #pragma unroll 2
        for (int t = 0; t < nf; ++t) {
            // exact 2^-e rescale keyed to v[0]'s exponent, on even steps only
            // (parity is static inside the unrolled pair; drift over 2 steps
            //  stays far inside fp32 range)
            float ps;
            if ((t & 1) == 0) {
                const float v0 = sh_v[cur][0];
                const int   eb = (int)(__float_as_uint(v0) >> 23);  // biased exp
                Mexp += eb - 127;
                ps = __expf(lp) *
                     __uint_as_float((unsigned)(254 - eb) << 23);
            } else {
                ps = __expf(lp);
            }

            const int   tn   = (t + 2 < TT) ? (t + 2) : (TT - 1);
            const float lpn2 = __ldg(lp_base + (long long)tn * FF); // prefetch d=2

            const ulonglong2* vp =
                reinterpret_cast<const ulonglong2*>(&sh_v[cur][0]);

            // 64 FFMA2 across 4 accumulators, q loaded in 2 chunks of 8
            unsigned long long a0 = 0ull, a1 = 0ull, a2 = 0ull, a3 = 0ull;
            #pragma unroll
            for (int g = 0; g < 2; ++g) {
                ulonglong2 q[16];
                #pragma unroll
                for (int i = 0; i < 16; ++i) q[i] = vp[16 * g + i];
                #pragma unroll
                for (int i = 0; i < 8; ++i) {
                    a0 = fma_f32x2(q[2 * i].x,     E2[32 * g + 4 * i + 0], a0);
                    a1 = fma_f32x2(q[2 * i].y,     E2[32 * g + 4 * i + 1], a1);
                    a2 = fma_f32x2(q[2 * i + 1].x, E2[32 * g + 4 * i + 2], a2);
                    a3 = fma_f32x2(q[2 * i + 1].y, E2[32 * g + 4 * i + 3], a3);
                }
            }
            a0 = add_f32x2(a0, a2);
            a1 = add_f32x2(a1, a3);
            a0 = add_f32x2(a0, a1);
            const float2 u = unpack2(a0);
            const float dot = u.x + u.y;

            sh_v[cur ^ 1][s] = dot * ps;
            lp  = lp1;
            lp1 = lpn2;
            __syncthreads();
            cur ^= 1;
        }

        // den = Mexp*ln2 + log(sum v)
        {
            float v = sh_v[cur][s];
            #pragma unroll
            for (int o = 16; o; o >>= 1) v += __shfl_xor_sync(0xffffffffu, v, o);
            if ((tid & 31) == 0) sh_wsum[tid >> 5] = v;
        }
        __syncthreads();
        if (tid == 0) {
            const float sv = sh_wsum[0] + sh_wsum[1] + sh_wsum[2] + sh_wsum[3];
            g_den[n] = (float)((double)Mexp * 0.6931471805599453 +
                               (double)logf(sv));
        }
    } else {
        // ============ numerator forward (log space), 2 states/thread ==========
        const int n  = b - NN;
        const int nf = sup[n * 3 + 2];
        const int qi = nlens[n];
        const int i  = tid;                 // 0..127; active i < 100

        // thread i owns states l0 = 2i+1 and l1 = 2i+2
        const float* lpb0 = nnet;  // dummy init
        const float* lpb1 = nnet;
        float lpA = 0.f, lpA1 = 0.f, lpB = 0.f, lpB1 = 0.f;

        if (i < 100) {
            const long long base = (long long)n * TT * FF;
            lpb0 = nnet + base + nlab[n * LL + 2 * i];       // emit for l0
            lpb1 = nnet + base + nlab[n * LL + 2 * i + 1];   // emit for l1
            lpA  = __ldg(lpb0);       lpB  = __ldg(lpb1);
            lpA1 = __ldg(lpb0 + FF);  lpB1 = __ldg(lpb1 + FF);
        }
        for (int j = i; j <= LL; j += 128) {
            sh_a[0][j] = (j == 0) ? 0.0f : NEGF;
            sh_a[1][j] = NEGF;
        }
        int cur = 0;
        __syncthreads();

        for (int t = 0; t < nf; ++t) {
            if (i < 100) {
                const float am = sh_a[cur][2 * i];       // old alpha[l0-1]
                const float a0 = sh_a[cur][2 * i + 1];   // old alpha[l0]
                const float a1 = sh_a[cur][2 * i + 2];   // old alpha[l1]

                const float h0 = fmaxf(a0, am), l0v = fminf(a0, am);
                const float nv0 = h0 + __logf(1.0f + __expf(l0v - h0)) + lpA;
                const float h1 = fmaxf(a1, a0), l1v = fminf(a1, a0);
                const float nv1 = h1 + __logf(1.0f + __expf(l1v - h1)) + lpB;

                const int   tn = (t + 2 < TT) ? (t + 2) : (TT - 1);
                const float pA = __ldg(lpb0 + (long long)tn * FF);
                const float pB = __ldg(lpb1 + (long long)tn * FF);

                sh_a[cur ^ 1][2 * i + 1] = nv0;
                sh_a[cur ^ 1][2 * i + 2] = nv1;
                if (i == 0) sh_a[cur ^ 1][0] = NEGF;     // alpha[0] = NEG each step
                lpA = lpA1; lpA1 = pA;
                lpB = lpB1; lpB1 = pB;
            }
            __syncthreads();
            cur ^= 1;
        }
        if (i == 0) g_num[n] = sh_a[cur][qi];
    }
}

__global__ void mmi_finalize(const int* __restrict__ sup, float* __restrict__ out)
{
    const int tid = threadIdx.x;  // 32 threads
    float tot = 0.f, fr = 0.f, af = 0.f;
    if (tid < NN) {
        const int nf = sup[tid * 3 + 2];
        const float t = g_num[tid] - g_den[tid];
        const bool fin = isfinite(t) && (t > 0.5f * NEGF);
        tot = fin ? t : 0.f;
        fr  = fin ? (float)nf : 0.f;
        af  = (float)nf;
    }
    #pragma unroll
    for (int o = 16; o; o >>= 1) {
        tot += __shfl_xor_sync(0xffffffffu, tot, o);
        fr  += __shfl_xor_sync(0xffffffffu, fr, o);
        af  += __shfl_xor_sync(0xffffffffu, af, o);
    }
    if (tid == 0) {
        out[0] = tot;
        out[1] = fr;
        out[2] = af;
    }
}

extern "C" void kernel_launch(void* const* d_in, const int* in_sizes, int n_in,
                              void* d_out, int out_size)
{
    const float* nnet  = (const float*)d_in[0];
    const int*   sup   = (const int*)  d_in[1];
    const float* trans = (const float*)d_in[2];
    const int*   dlab  = (const int*)  d_in[3];
    const int*   nlab  = (const int*)  d_in[4];
    const int*   nlens = (const int*)  d_in[5];

    mmi_forward<<<2 * NN, 128>>>(nnet, sup, trans, dlab, nlab, nlens);
    mmi_finalize<<<1, 32>>>(sup, (float*)d_out);
}